// round 9
// baseline (speedup 1.0000x reference)
#include <cuda_runtime.h>
#include <cstdint>

// Problem constants (fixed by the dataset)
#define NN      100000      // nodes
#define EMAX    1600000     // edges
#define DIN     256         // input feature dim
#define DOUT    32          // output feature dim
#define GTHREADS 256        // 8 warps
#define RPW     16          // rows per warp (m16)
#define RPB     (RPW * 8)   // 128 rows per block
#define NKS     (DIN / 8)   // 32 k-steps of k8
#define CHUNK_COLS 32       // k-columns per pipeline chunk
#define KSPC    4           // k-steps per chunk
#define NCHUNK  (DIN / CHUNK_COLS)   // 8
#define XS_STRIDE 36        // floats per staged row (bank-spread, 16B aligned)
#define XBUF_FLOATS (RPB * XS_STRIDE)
#define BFRAG_N (NKS * 4 * 32)                  // 4096 uint2
#define BFRAG_BYTES (BFRAG_N * 8)               // 32 KB
#define SMEM_BYTES  (BFRAG_BYTES + 2 * XBUF_FLOATS * 4)

#define NBCHUNK 2048
#define NSCAN_BLOCKS ((NN + NBCHUNK - 1) / NBCHUNK)   // 49

// ---- Device-global scratch (per rules) ----
__device__ float g_presup[(size_t)NN * DOUT];   // 12.8 MB
__device__ uint2 g_bfrag[BFRAG_N];              // 32 KB
__device__ int   g_count[NN];
__device__ int   g_rowptr[NN + 1];
__device__ int   g_cursor[NN];
__device__ int   g_part[NSCAN_BLOCKS + 1];
__device__ int   g_ecol[EMAX];
__device__ float g_eval[EMAX];

// ===========================================================================
// GEMM (tf32 mma.sync) -- as Round 8, but Bfrag precomputed once to global.
// ===========================================================================
__device__ __forceinline__ uint32_t f2tf32(float f) {
    uint32_t u;
    asm("cvt.rna.tf32.f32 %0, %1;" : "=r"(u) : "f"(f));
    return u;
}

__device__ __forceinline__ void mma_tf32(float4& d,
                                         uint32_t a0, uint32_t a1, uint32_t a2, uint32_t a3,
                                         uint32_t b0, uint32_t b1) {
    asm volatile("mma.sync.aligned.m16n8k8.row.col.f32.tf32.tf32.f32 "
                 "{%0,%1,%2,%3}, {%4,%5,%6,%7}, {%8,%9}, {%0,%1,%2,%3};"
                 : "+f"(d.x), "+f"(d.y), "+f"(d.z), "+f"(d.w)
                 : "r"(a0), "r"(a1), "r"(a2), "r"(a3), "r"(b0), "r"(b1));
}

__device__ __forceinline__ uint32_t smem_u32(const void* p) {
    uint32_t a;
    asm("{ .reg .u64 t; cvta.to.shared.u64 t, %1; cvt.u32.u64 %0, t; }"
        : "=r"(a) : "l"(p));
    return a;
}

__device__ __forceinline__ void cp_async16(uint32_t dst, const void* src, int nbytes) {
    asm volatile("cp.async.ca.shared.global [%0], [%1], 16, %2;"
                 :: "r"(dst), "l"(src), "r"(nbytes) : "memory");
}

__device__ __forceinline__ void issue_chunk(uint32_t xs_addr, const float* __restrict__ x,
                                            int row0, int kc, int tid) {
#pragma unroll
    for (int j = 0; j < 4; j++) {
        int i    = tid + j * GTHREADS;
        int r    = i >> 3;
        int seg  = i & 7;
        int grow = row0 + r;
        int gsrc = (grow < NN) ? grow : (NN - 1);
        const float* src = x + (size_t)gsrc * DIN + kc + seg * 4;
        uint32_t dst = xs_addr + (uint32_t)(r * (XS_STRIDE * 4) + seg * 16);
        cp_async16(dst, src, (grow < NN) ? 16 : 0);
    }
    asm volatile("cp.async.commit_group;" ::: "memory");
}

// Precompute B fragments once (grid 16 x 256)
__global__ void bfrag_kernel(const float* __restrict__ w) {
    int i = blockIdx.x * 256 + threadIdx.x;
    if (i >= BFRAG_N) return;
    int ks  = i >> 7;
    int rem = i & 127;
    int nb  = rem >> 5;
    int ln  = rem & 31;
    int t = ln & 3, g = ln >> 2;
    float w0 = w[(ks * 8 + t)     * DOUT + nb * 8 + g];
    float w1 = w[(ks * 8 + t + 4) * DOUT + nb * 8 + g];
    g_bfrag[i] = make_uint2(f2tf32(w0), f2tf32(w1));
}

__global__ __launch_bounds__(GTHREADS, 3) void gemm_kernel(const float* __restrict__ x) {
    extern __shared__ char smem[];
    uint2* Bfrag = (uint2*)smem;                         // 32 KB
    float* Xbuf  = (float*)(smem + BFRAG_BYTES);
    const uint32_t xb_addr0 = smem_u32(Xbuf);
    const uint32_t xb_addr1 = xb_addr0 + XBUF_FLOATS * 4;

    const int tid  = threadIdx.x;
    const int row0 = blockIdx.x * RPB;

    issue_chunk(xb_addr0, x, row0, 0,          tid);
    issue_chunk(xb_addr1, x, row0, CHUNK_COLS, tid);

    // Linear copy of precomputed B fragments (coalesced LDG.128)
    {
        const uint4* src = (const uint4*)g_bfrag;
        uint4* dst = (uint4*)Bfrag;
#pragma unroll
        for (int i = 0; i < BFRAG_N / 2 / GTHREADS; i++)
            dst[tid + i * GTHREADS] = src[tid + i * GTHREADS];
    }

    const int wid  = tid >> 5;
    const int lane = tid & 31;
    const int t    = lane & 3;
    const int g    = lane >> 2;
    const int rl   = wid * RPW;

    float4 acc[4];
#pragma unroll
    for (int nb = 0; nb < 4; nb++) acc[nb] = make_float4(0.f, 0.f, 0.f, 0.f);

    const int offA = (rl + g) * XS_STRIDE + t;
    const int offB = (rl + g + 8) * XS_STRIDE + t;

#pragma unroll
    for (int c = 0; c < NCHUNK; c++) {
        if (c < NCHUNK - 1)
            asm volatile("cp.async.wait_group 1;" ::: "memory");
        else
            asm volatile("cp.async.wait_group 0;" ::: "memory");
        __syncthreads();

        const float* Xs = Xbuf + (c & 1) * XBUF_FLOATS;
#pragma unroll
        for (int ksl = 0; ksl < KSPC; ksl++) {
            const int k0 = ksl * 8;
            uint32_t a0 = f2tf32(Xs[offA + k0]);
            uint32_t a1 = f2tf32(Xs[offB + k0]);
            uint32_t a2 = f2tf32(Xs[offA + k0 + 4]);
            uint32_t a3 = f2tf32(Xs[offB + k0 + 4]);

            const uint2* bp = Bfrag + (c * KSPC + ksl) * 4 * 32 + lane;
            uint2 b0 = bp[0 * 32];
            uint2 b1 = bp[1 * 32];
            uint2 b2 = bp[2 * 32];
            uint2 b3 = bp[3 * 32];
            mma_tf32(acc[0], a0, a1, a2, a3, b0.x, b0.y);
            mma_tf32(acc[1], a0, a1, a2, a3, b1.x, b1.y);
            mma_tf32(acc[2], a0, a1, a2, a3, b2.x, b2.y);
            mma_tf32(acc[3], a0, a1, a2, a3, b3.x, b3.y);
        }

        if (c + 2 < NCHUNK) {
            __syncthreads();
            issue_chunk((c & 1) ? xb_addr1 : xb_addr0, x, row0,
                        (c + 2) * CHUNK_COLS, tid);
        }
    }

    const int r0 = row0 + rl + g;
    const int r1 = row0 + rl + g + 8;
#pragma unroll
    for (int nb = 0; nb < 4; nb++) {
        if (r0 < NN)
            *(float2*)(g_presup + (size_t)r0 * DOUT + nb * 8 + 2 * t) =
                make_float2(acc[nb].x, acc[nb].y);
        if (r1 < NN)
            *(float2*)(g_presup + (size_t)r1 * DOUT + nb * 8 + 2 * t) =
                make_float2(acc[nb].z, acc[nb].w);
    }
}

// ===========================================================================
// CSR build: zero -> histogram -> 3-phase exclusive scan -> reorder
// ===========================================================================
__global__ __launch_bounds__(256) void zero_kernel() {
    int i = blockIdx.x * 256 + threadIdx.x;
    if (i < NN) g_count[i] = 0;
}

__global__ __launch_bounds__(256) void hist_kernel(const int* __restrict__ arow, int n_edges) {
    int e = blockIdx.x * 256 + threadIdx.x;
    if (e < n_edges) atomicAdd(&g_count[arow[e]], 1);
}

__device__ __forceinline__ int warp_excl_scan(int v, int lane, int& total) {
    int inc = v;
#pragma unroll
    for (int d = 1; d < 32; d <<= 1) {
        int n = __shfl_up_sync(0xFFFFFFFFu, inc, d);
        if (lane >= d) inc += n;
    }
    total = __shfl_sync(0xFFFFFFFFu, inc, 31);
    return inc - v;
}

// Phase 1: per-chunk (2048) exclusive scan; chunk totals -> g_part
__global__ __launch_bounds__(256) void scan1_kernel() {
    __shared__ int wsum[8], woff[8];
    const int tid = threadIdx.x, lane = tid & 31, wid = tid >> 5;
    const int base = blockIdx.x * NBCHUNK + tid * 8;

    int v[8], t = 0;
#pragma unroll
    for (int j = 0; j < 8; j++) {
        int idx = base + j;
        v[j] = (idx < NN) ? g_count[idx] : 0;
        t += v[j];
    }
    int wt;
    int texcl = warp_excl_scan(t, lane, wt);
    if (lane == 31) wsum[wid] = wt;
    __syncthreads();
    if (wid == 0) {
        int s = (lane < 8) ? wsum[lane] : 0;
        int st;
        int se = warp_excl_scan(s, lane, st);
        if (lane < 8) woff[lane] = se;
        if (lane == 0) g_part[blockIdx.x] = st;
    }
    __syncthreads();
    int off = woff[wid] + texcl;
#pragma unroll
    for (int j = 0; j < 8; j++) {
        int idx = base + j;
        if (idx < NN) g_rowptr[idx] = off;
        off += v[j];
    }
}

// Phase 2: exclusive scan of the 49 chunk totals (single block, 64 threads)
__global__ void scan2_kernel() {
    __shared__ int w0total;
    const int tid = threadIdx.x, lane = tid & 31, wid = tid >> 5;
    int v = (tid < NSCAN_BLOCKS) ? g_part[tid] : 0;
    int wt;
    int e = warp_excl_scan(v, lane, wt);
    if (wid == 0 && lane == 0) w0total = wt;
    __syncthreads();
    int off = (wid == 1) ? w0total : 0;
    if (tid < NSCAN_BLOCKS) g_part[tid] = e + off;
}

// Phase 3: add chunk offsets; init cursors; set rowptr[NN]
__global__ __launch_bounds__(256) void scan3_kernel(int n_edges) {
    int i = blockIdx.x * 256 + threadIdx.x;
    if (i < NN) {
        int rp = g_rowptr[i] + g_part[i >> 11];   // NBCHUNK = 2048
        g_rowptr[i] = rp;
        g_cursor[i] = rp;
    }
    if (i == 0) g_rowptr[NN] = n_edges;
}

__global__ __launch_bounds__(256) void reorder_kernel(const int*   __restrict__ arow,
                                                      const int*   __restrict__ acol,
                                                      const float* __restrict__ aval,
                                                      int n_edges) {
    int e = blockIdx.x * 256 + threadIdx.x;
    if (e >= n_edges) return;
    int r   = arow[e];
    int pos = atomicAdd(&g_cursor[r], 1);
    g_ecol[pos] = acol[e];
    g_eval[pos] = aval[e];
}

// ===========================================================================
// SpMM (CSR) + fused ReLU: one warp per row, lane = output column.
// ===========================================================================
__global__ __launch_bounds__(256) void spmm_kernel(float* __restrict__ out) {
    const int wid  = threadIdx.x >> 5;
    const int lane = threadIdx.x & 31;
    const int r    = blockIdx.x * 8 + wid;
    if (r >= NN) return;

    int e   = g_rowptr[r];
    int end = g_rowptr[r + 1];
    float acc = 0.f;

    // 2-deep software prefetch of (col, val) for ILP
    for (; e + 1 < end; e += 2) {
        int   c0 = g_ecol[e],     c1 = g_ecol[e + 1];
        float v0 = g_eval[e],     v1 = g_eval[e + 1];
        float p0 = g_presup[(size_t)c0 * DOUT + lane];
        float p1 = g_presup[(size_t)c1 * DOUT + lane];
        acc = fmaf(v0, p0, acc);
        acc = fmaf(v1, p1, acc);
    }
    if (e < end) {
        int   c = g_ecol[e];
        float v = g_eval[e];
        acc = fmaf(v, g_presup[(size_t)c * DOUT + lane], acc);
    }

    out[(size_t)r * DOUT + lane] = fmaxf(acc, 0.f);
}

// ===========================================================================
// kernel_launch
// ===========================================================================
extern "C" void kernel_launch(void* const* d_in, const int* in_sizes, int n_in,
                              void* d_out, int out_size) {
    const float* x    = (const float*)d_in[0];
    const int*   arow = (const int*)  d_in[1];
    const int*   acol = (const int*)  d_in[2];
    const float* aval = (const float*)d_in[3];
    const float* w    = (const float*)d_in[4];
    float*       out  = (float*)d_out;

    const int n_edges = in_sizes[1];
    const int eblocks = (n_edges + 255) / 256;

    cudaFuncSetAttribute(gemm_kernel, cudaFuncAttributeMaxDynamicSharedMemorySize,
                         SMEM_BYTES);

    bfrag_kernel<<<(BFRAG_N + 255) / 256, 256>>>(w);
    zero_kernel<<<(NN + 255) / 256, 256>>>();
    hist_kernel<<<eblocks, 256>>>(arow, n_edges);
    gemm_kernel<<<(NN + RPB - 1) / RPB, GTHREADS, SMEM_BYTES>>>(x);
    scan1_kernel<<<NSCAN_BLOCKS, 256>>>();
    scan2_kernel<<<1, 64>>>();
    scan3_kernel<<<(NN + 255) / 256, 256>>>(n_edges);
    reorder_kernel<<<eblocks, 256>>>(arow, acol, aval, n_edges);
    spmm_kernel<<<(NN + 7) / 8, 256>>>(out);
}